// round 11
// baseline (speedup 1.0000x reference)
#include <cuda_runtime.h>
#include <cstdint>

#define N_NODES 50000
#define A_DIM   65
#define DEG     32
#define HID     16
#define BOT     32
#define WARPS_PER_BLOCK 4

typedef unsigned long long u64;

// Only W2 lives in the constant bank: the hot 128-LDC.128/warp stream.
__constant__ float cW2[HID * BOT];     // [16][32] row-major
// Composed layer-1 weights, written once by the setup kernel.
__device__ float4 g_L1[HID];           // (Wc0[j], Wc1[j], bc[j], 0)

__global__ void setup_weights_kernel(const float* __restrict__ W_se,
                                     const float* __restrict__ b_se,
                                     const float* __restrict__ W1,
                                     const float* __restrict__ b1) {
    int t = threadIdx.x;
    if (t < HID) {
        float wc0 = 0.f, wc1 = 0.f, bc = b1[t];
        #pragma unroll
        for (int e = 0; e < 32; e++) {
            float w1ej = W1[e * HID + t];
            wc0 = fmaf(W_se[e],      w1ej, wc0);
            wc1 = fmaf(W_se[32 + e], w1ej, wc1);
            bc  = fmaf(b_se[e],      w1ej, bc);
        }
        g_L1[t] = make_float4(wc0, wc1, bc, 0.f);
    }
}

__device__ __forceinline__ void fma2(u64& acc, u64 a, u64 b) {
    asm("fma.rn.f32x2 %0, %1, %2, %0;" : "+l"(acc) : "l"(a), "l"(b));
}
__device__ __forceinline__ u64 pack2(float v) {
    u64 r;
    asm("mov.b64 %0, {%1, %1};" : "=l"(r) : "r"(__float_as_uint(v)));
    return r;
}

// Per-node epilogue region: 32 neighbor-rows x 9 u64 (8 data + 1 pad) = 288,
// +8 u64 pad between node regions (bank-complementary reduce lanes).
#define NODE_STRIDE 296

__global__ __launch_bounds__(WARPS_PER_BLOCK * 32, 6)
void pooling_net_kernel(const float2* __restrict__ corr,   // [N, 65]
                        const int*    __restrict__ nei,    // [N*32, 3]
                        const float*  __restrict__ b2g,    // [32]
                        float*        __restrict__ out) {  // [N, 32]
    __shared__ u64 red[WARPS_PER_BLOCK][2 * NODE_STRIDE];
    __shared__ float4 sL1[HID];        // composed layer-1 (256B)
    __shared__ u64   sb2[16];          // b2 as f32x2 pairs (128B)

    int warp = (blockIdx.x * blockDim.x + threadIdx.x) >> 5;
    int lane = threadIdx.x & 31;
    int wl   = threadIdx.x >> 5;
    int n0   = warp * 2;
    bool alive = (n0 < N_NODES);
    int n1   = n0 + 1;

    // Issue gathers FIRST so their DRAM latency hides under the staging sync
    int aA = 0, aB = 0;
    float2 xA = make_float2(0.f, 0.f), xB = xA;
    if (alive) {
        aA = nei[(n0 * DEG + lane) * 3 + 1];
        aB = nei[(n1 * DEG + lane) * 3 + 1];
        xA = corr[n0 * A_DIM + aA];
        xB = corr[n1 * A_DIM + aB];
    }

    // Cheap staging: two cache lines of LDG, no compute chain
    {
        int t = threadIdx.x;
        if (t < HID)                sL1[t]      = g_L1[t];
        else if (t >= 32 && t < 48) sb2[t - 32] = ((const u64*)b2g)[t - 32];
    }
    __syncthreads();
    if (!alive) return;

    // Layer 1 (composed 2->16) + relu, both nodes (weights via 16 LDS.128 broadcasts)
    float h1A[HID], h1B[HID];
    #pragma unroll
    for (int j = 0; j < HID; j++) {
        float4 p = sL1[j];
        h1A[j] = fmaxf(fmaf(xA.x, p.x, fmaf(xA.y, p.y, p.z)), 0.f);
        h1B[j] = fmaxf(fmaf(xB.x, p.x, fmaf(xB.y, p.y, p.z)), 0.f);
    }

    int node = lane >> 4;          // reduce role: 0 -> node n0, 1 -> node n1
    int ch   = lane & 15;
    const float* rbase = (const float*)&red[wl][node * NODE_STRIDE];

    #pragma unroll
    for (int half = 0; half < 2; half++) {
        // Channels [half*16, half*16+16): 8 packed f32x2 accs per node
        u64 accA[8], accB[8];
        #pragma unroll
        for (int c = 0; c < 8; c++) {
            u64 b = sb2[half * 8 + c];
            accA[c] = b; accB[c] = b;
        }

        const ulonglong2* w2v = (const ulonglong2*)cW2 + half * 4;
        #pragma unroll
        for (int j = 0; j < HID; j++) {
            u64 mA = pack2(h1A[j]);
            u64 mB = pack2(h1B[j]);
            #pragma unroll
            for (int cc = 0; cc < 4; cc++) {
                ulonglong2 w = w2v[j * 8 + cc];             // LDC.128 (const port)
                fma2(accA[2 * cc],     mA, w.x);
                fma2(accA[2 * cc + 1], mA, w.y);
                fma2(accB[2 * cc],     mB, w.x);
                fma2(accB[2 * cc + 1], mB, w.y);
            }
        }

        // Transpose both nodes' half through shared; relu folded into max(0, ...)
        u64* rA = &red[wl][0 * NODE_STRIDE + lane * 9];
        u64* rB = &red[wl][1 * NODE_STRIDE + lane * 9];
        #pragma unroll
        for (int c = 0; c < 8; c++) { rA[c] = accA[c]; rB[c] = accB[c]; }
        __syncwarp();

        float m = 0.f;
        #pragma unroll
        for (int d = 0; d < DEG; d++)
            m = fmaxf(m, rbase[d * 18 + ch]);
        out[(n0 + node) * BOT + half * 16 + ch] = m;
        __syncwarp();
    }
}

extern "C" void kernel_launch(void* const* d_in, const int* in_sizes, int n_in,
                              void* d_out, int out_size) {
    const float* corr  = (const float*)d_in[0];   // [N, 65, 2]
    const int*   nei   = (const int*)d_in[1];     // [N*32, 3]
    // d_in[2] = lstm_state (dead)
    const float* W_se  = (const float*)d_in[3];
    const float* b_se  = (const float*)d_in[4];
    const float* W1    = (const float*)d_in[5];
    const float* b1    = (const float*)d_in[6];
    const float* W2    = (const float*)d_in[7];
    const float* b2    = (const float*)d_in[8];
    float* out = (float*)d_out;

    setup_weights_kernel<<<1, 32>>>(W_se, b_se, W1, b1);

    // Raw W2 straight into the constant bank (independent of the setup kernel)
    cudaMemcpyToSymbolAsync(cW2, W2, HID * BOT * sizeof(float), 0,
                            cudaMemcpyDeviceToDevice, 0);

    int warps  = (N_NODES + 1) / 2;
    int blocks = (warps + WARPS_PER_BLOCK - 1) / WARPS_PER_BLOCK;
    pooling_net_kernel<<<blocks, WARPS_PER_BLOCK * 32>>>(
        (const float2*)corr, nei, b2, out);
}

// round 12
// speedup vs baseline: 1.0617x; 1.0617x over previous
#include <cuda_runtime.h>
#include <cstdint>

#define N_NODES 50000
#define A_DIM   65
#define DEG     32
#define HID     16
#define BOT     32
#define WARPS_PER_BLOCK 4

typedef unsigned long long u64;

// Only W2 lives in the constant bank: the hot 128-LDC.128/warp stream.
__constant__ float cW2[HID * BOT];     // [16][32] row-major
// Composed layer-1 weights, written once by the setup kernel.
__device__ float4 g_L1[HID];           // (Wc0[j], Wc1[j], bc[j], 0)

__global__ void setup_weights_kernel(const float* __restrict__ W_se,
                                     const float* __restrict__ b_se,
                                     const float* __restrict__ W1,
                                     const float* __restrict__ b1) {
    int t = threadIdx.x;
    if (t < HID) {
        float wc0 = 0.f, wc1 = 0.f, bc = b1[t];
        #pragma unroll
        for (int e = 0; e < 32; e++) {
            float w1ej = W1[e * HID + t];
            wc0 = fmaf(W_se[e],      w1ej, wc0);
            wc1 = fmaf(W_se[32 + e], w1ej, wc1);
            bc  = fmaf(b_se[e],      w1ej, bc);
        }
        g_L1[t] = make_float4(wc0, wc1, bc, 0.f);
    }
}

__device__ __forceinline__ void fma2(u64& acc, u64 a, u64 b) {
    asm("fma.rn.f32x2 %0, %1, %2, %0;" : "+l"(acc) : "l"(a), "l"(b));
}
__device__ __forceinline__ u64 pack2(float v) {
    u64 r;
    asm("mov.b64 %0, {%1, %1};" : "=l"(r) : "r"(__float_as_uint(v)));
    return r;
}

// Per-node epilogue region: 32 neighbor-rows x 9 u64 (8 data + 1 pad) = 288,
// +8 u64 pad between node regions (bank-complementary reduce lanes).
#define NODE_STRIDE 296

__global__ __launch_bounds__(WARPS_PER_BLOCK * 32, 6)
void pooling_net_kernel(const float2* __restrict__ corr,   // [N, 65]
                        const int*    __restrict__ nei,    // [N*32, 3]
                        const float*  __restrict__ b2g,    // [32]
                        float*        __restrict__ out) {  // [N, 32]
    __shared__ u64 red[WARPS_PER_BLOCK][2 * NODE_STRIDE];
    __shared__ float4 sL1[HID];        // composed layer-1 (256B)
    __shared__ u64   sb2[16];          // b2 as f32x2 pairs (128B)

    int warp = (blockIdx.x * blockDim.x + threadIdx.x) >> 5;
    int lane = threadIdx.x & 31;
    int wl   = threadIdx.x >> 5;
    int n0   = warp * 2;
    bool alive = (n0 < N_NODES);
    int n1   = n0 + 1;

    // Issue gathers FIRST so their DRAM latency hides under the staging sync
    int aA = 0, aB = 0;
    float2 xA = make_float2(0.f, 0.f), xB = xA;
    if (alive) {
        aA = nei[(n0 * DEG + lane) * 3 + 1];
        aB = nei[(n1 * DEG + lane) * 3 + 1];
        xA = corr[n0 * A_DIM + aA];
        xB = corr[n1 * A_DIM + aB];
    }

    // Cheap staging: two cache lines of LDG, no compute chain
    {
        int t = threadIdx.x;
        if (t < HID)                sL1[t]      = g_L1[t];
        else if (t >= 32 && t < 48) sb2[t - 32] = ((const u64*)b2g)[t - 32];
    }
    __syncthreads();
    if (!alive) return;

    // Layer 1 (composed 2->16) + relu, both nodes (weights via 16 LDS.128 broadcasts)
    float h1A[HID], h1B[HID];
    #pragma unroll
    for (int j = 0; j < HID; j++) {
        float4 p = sL1[j];
        h1A[j] = fmaxf(fmaf(xA.x, p.x, fmaf(xA.y, p.y, p.z)), 0.f);
        h1B[j] = fmaxf(fmaf(xB.x, p.x, fmaf(xB.y, p.y, p.z)), 0.f);
    }

    int node = lane >> 4;          // reduce role: 0 -> node n0, 1 -> node n1
    int ch   = lane & 15;
    const float* rbase = (const float*)&red[wl][node * NODE_STRIDE];

    #pragma unroll
    for (int half = 0; half < 2; half++) {
        // Channels [half*16, half*16+16): 8 packed f32x2 accs per node
        u64 accA[8], accB[8];
        #pragma unroll
        for (int c = 0; c < 8; c++) {
            u64 b = sb2[half * 8 + c];
            accA[c] = b; accB[c] = b;
        }

        const ulonglong2* w2v = (const ulonglong2*)cW2 + half * 4;
        #pragma unroll
        for (int j = 0; j < HID; j++) {
            u64 mA = pack2(h1A[j]);
            u64 mB = pack2(h1B[j]);
            #pragma unroll
            for (int cc = 0; cc < 4; cc++) {
                ulonglong2 w = w2v[j * 8 + cc];             // LDC.128 (const port)
                fma2(accA[2 * cc],     mA, w.x);
                fma2(accA[2 * cc + 1], mA, w.y);
                fma2(accB[2 * cc],     mB, w.x);
                fma2(accB[2 * cc + 1], mB, w.y);
            }
        }

        // Transpose both nodes' half through shared; relu folded into max(0, ...)
        u64* rA = &red[wl][0 * NODE_STRIDE + lane * 9];
        u64* rB = &red[wl][1 * NODE_STRIDE + lane * 9];
        #pragma unroll
        for (int c = 0; c < 8; c++) { rA[c] = accA[c]; rB[c] = accB[c]; }
        __syncwarp();

        float m = 0.f;
        #pragma unroll
        for (int d = 0; d < DEG; d++)
            m = fmaxf(m, rbase[d * 18 + ch]);
        out[(n0 + node) * BOT + half * 16 + ch] = m;
        __syncwarp();
    }
}

extern "C" void kernel_launch(void* const* d_in, const int* in_sizes, int n_in,
                              void* d_out, int out_size) {
    const float* corr  = (const float*)d_in[0];   // [N, 65, 2]
    const int*   nei   = (const int*)d_in[1];     // [N*32, 3]
    // d_in[2] = lstm_state (dead)
    const float* W_se  = (const float*)d_in[3];
    const float* b_se  = (const float*)d_in[4];
    const float* W1    = (const float*)d_in[5];
    const float* b1    = (const float*)d_in[6];
    const float* W2    = (const float*)d_in[7];
    const float* b2    = (const float*)d_in[8];
    float* out = (float*)d_out;

    setup_weights_kernel<<<1, 32>>>(W_se, b_se, W1, b1);

    // Raw W2 straight into the constant bank (independent of the setup kernel)
    cudaMemcpyToSymbolAsync(cW2, W2, HID * BOT * sizeof(float), 0,
                            cudaMemcpyDeviceToDevice, 0);

    int warps  = (N_NODES + 1) / 2;
    int blocks = (warps + WARPS_PER_BLOCK - 1) / WARPS_PER_BLOCK;
    pooling_net_kernel<<<blocks, WARPS_PER_BLOCK * 32>>>(
        (const float2*)corr, nei, b2, out);
}